// round 10
// baseline (speedup 1.0000x reference)
#include <cuda_runtime.h>
#include <stdint.h>
#include <math.h>

// ---------------------------------------------------------------------------
// InstanceLossBoost pseudo-label update.
//   inputs : c[B,K] f32, pseudo_label_cur[B] i32, index[B] i32   (K=128, B=2M)
//   output : float32 buffer = [ final[B] , index[B] ]  (values cast to float)
//
// Two launches:
//   k1_main : warp-per-row argmax (float4 streaming loads, REDUX). Argmax
//             results are warp-uniform, so lane t captures row (wbase+t)'s
//             result and the warp stages its own 32 rows directly — no smem
//             staging, no per-chunk block syncs, and NO scratch store.
//             Last block performs class-init from the per-class histogram.
//   kSel    : rare-path kernel (software grid barriers). If any class exceeds
//             the quota it RECOMPUTES packed (rel,pred) from c into g_cp, then
//             exact per-class top-PPC radix select (2 x 9-bit passes over
//             float bits in [bits(0.99), bits(1.0)]) + index tie-break +
//             output fixup. Early-exits otherwise; self-cleans all scratch.
// ---------------------------------------------------------------------------

#define ALPHA_F   0.99f
#define KMAX      256
#define NBINS     512
#define TIE_CAP   16384
#define BCAP      (1 << 22)
#define NB_SEL    128

// packed per-row scratch (rare path only): 0 if conf < alpha,
// else ((rel_bits + 1) << 7) | pred ; rel_bits = bits(conf) - bits(0.99f)
__device__ unsigned int  g_cp[BCAP];                 // 16 MB (rare path only)
__device__ int           g_hist[KMAX];               // zeroed by class-init
__device__ int           g_active[KMAX];
__device__ int           g_needtie[KMAX];            // zeroed by kSel cleanup
__device__ unsigned int  g_thrrel[KMAX];
__device__ int           g_radmit[KMAX];
__device__ int           g_sel1[KMAX];
__device__ int           g_rem[KMAX];
__device__ int           g_h1[KMAX * NBINS];         // zeroed by kSel cleanup
__device__ int           g_h2[KMAX * NBINS];         // zeroed by kSel cleanup
__device__ int           g_tiecnt[KMAX];             // zeroed by kSel cleanup
__device__ int           g_tied[KMAX * TIE_CAP];     // 16 MB
__device__ int           g_nactive;
__device__ int           g_ntie;
__device__ unsigned int  g_done1;                    // k1 completion counter
__device__ unsigned int  g_bar_cnt;
__device__ volatile unsigned int g_bar_gen;

// --------------------------- software grid barrier --------------------------
__device__ __forceinline__ void grid_barrier() {
    __syncthreads();
    if (threadIdx.x == 0) {
        __threadfence();
        unsigned gen = g_bar_gen;
        if (atomicAdd(&g_bar_cnt, 1) == gridDim.x - 1) {
            g_bar_cnt = 0;
            __threadfence();
            g_bar_gen = gen + 1;
        } else {
            while (g_bar_gen == gen) { }
            __threadfence();
        }
    }
    __syncthreads();
}

// ------------------ per-class init (fused into k1 tail) ---------------------
__device__ __forceinline__ void class_init_body(int K, int PPC) {
    int k = threadIdx.x;
    int act = 0;
    if (k < KMAX) {
        int h = (k < K) ? g_hist[k] : 0;
        g_hist[k]   = 0;                 // self-clean for next replay
        act = (h > PPC) ? 1 : 0;
        g_active[k] = act;
        g_thrrel[k] = 0u;
        g_rem[k]    = PPC;
        g_sel1[k]   = -1;
        g_radmit[k] = 0;
    }
    int na = __syncthreads_count(act);
    if (threadIdx.x == 0) g_nactive = na;
}

// ---------------------- warp argmax over one row (K=128) --------------------
// REDUX.max on float bits (softmax values non-negative) + ballot + 1 shuffle.
// Result (conf, pred) is WARP-UNIFORM. Tie rule = lowest column index.
__device__ __forceinline__ void argmax_row(const float4 v, float& conf, int& pred) {
    float m  = fmaxf(fmaxf(v.x, v.y), fmaxf(v.z, v.w));
    unsigned wb = __reduce_max_sync(0xffffffffu, __float_as_uint(m));
    float wm = __uint_as_float(wb);
    int local = 4;
    if (v.w == wm) local = 3;
    if (v.z == wm) local = 2;
    if (v.y == wm) local = 1;
    if (v.x == wm) local = 0;
    unsigned mask = __ballot_sync(0xffffffffu, local < 4);
    int src = __ffs(mask) - 1;
    int li  = __shfl_sync(0xffffffffu, local, src);
    conf = wm;
    pred = src * 4 + li;
}

__global__ void k1_main(const float* __restrict__ c,
                        const int*   __restrict__ cur,
                        const int*   __restrict__ idx,
                        float*       __restrict__ out,
                        int B, int writeIdx, int K, int PPC) {
    __shared__ int s_hist[128];
    __shared__ int s_last;

    for (int t = threadIdx.x; t < 128; t += blockDim.x) s_hist[t] = 0;
    __syncthreads();

    const int warp = threadIdx.x >> 5;
    const int lane = threadIdx.x & 31;
    const int warpsPerBlock = blockDim.x >> 5;
    const int gwarp   = blockIdx.x * warpsPerBlock + warp;
    const int nWarpsT = gridDim.x * warpsPerBlock;
    const int nGroups = (B + 31) >> 5;          // groups of 32 rows

    for (int g = gwarp; g < nGroups; g += nWarpsT) {
        const int wbase  = g << 5;
        const int r_lane = wbase + lane;
        const bool inb   = (r_lane < B);

        // prefetch staging operands under the row loads
        int cv = 0, iv = 0;
        if (inb) {
            cv = __ldcs(cur + r_lane);
            if (writeIdx) iv = __ldcs(idx + r_lane);
        }

        float myconf = 0.0f; int mypred = 0;

        if (wbase + 32 <= B) {
            // full group: 2 rows in flight, lane t captures row wbase+t
            #pragma unroll 2
            for (int t = 0; t < 32; t += 2) {
                const float4 a = __ldcs(reinterpret_cast<const float4*>(
                                     c + (size_t)(wbase + t) * 128) + lane);
                const float4 b = __ldcs(reinterpret_cast<const float4*>(
                                     c + (size_t)(wbase + t + 1) * 128) + lane);
                float c0, c1; int p0, p1;
                argmax_row(a, c0, p0);
                argmax_row(b, c1, p1);
                if (lane == t)     { myconf = c0; mypred = p0; }
                if (lane == t + 1) { myconf = c1; mypred = p1; }
            }
        } else {
            for (int t = 0; t < 32; ++t) {
                int r = wbase + t;
                if (r < B) {
                    const float4 v = __ldcs(reinterpret_cast<const float4*>(
                                         c + (size_t)r * 128) + lane);
                    float cf; int pv;
                    argmax_row(v, cf, pv);
                    if (lane == t) { myconf = cf; mypred = pv; }
                }
            }
        }

        // staging: warp handles its own 32 rows, fully coalesced
        if (inb) {
            bool hi = !(myconf < ALPHA_F);
            if (hi) atomicAdd(&s_hist[mypred], 1);
            __stcs(&out[r_lane],
                   hi ? (cv != -1 ? (float)cv : (float)mypred) : -1.0f);
            if (writeIdx) __stcs(&out[B + r_lane], (float)iv);
        }
    }

    __syncthreads();
    for (int t = threadIdx.x; t < 128; t += blockDim.x) {
        int v = s_hist[t];
        if (v) atomicAdd(&g_hist[t], v);
    }

    // ---- fused class init: last block to finish does it ----
    __threadfence();
    __syncthreads();
    if (threadIdx.x == 0) {
        unsigned t = atomicAdd(&g_done1, 1);
        s_last = (t == gridDim.x - 1) ? 1 : 0;
    }
    __syncthreads();
    if (s_last) {
        if (threadIdx.x == 0) g_done1 = 0;   // reset for next replay
        class_init_body(K, PPC);
    }
}

// --------------------- generic fallback (K != 128) --------------------------
__global__ void k1_generic(const float* __restrict__ c,
                           const int*   __restrict__ cur,
                           const int*   __restrict__ idx,
                           float*       __restrict__ out,
                           int B, int K, int writeIdx) {
    const unsigned LOW = __float_as_uint(ALPHA_F);
    int stride = gridDim.x * blockDim.x;
    for (int i = blockIdx.x * blockDim.x + threadIdx.x; i < B; i += stride) {
        const float* row = c + (size_t)i * K;
        float best = row[0]; int bi = 0;
        for (int j = 1; j < K; ++j) {
            float v = row[j];
            if (v > best) { best = v; bi = j; }
        }
        bool hi = !(best < ALPHA_F);
        unsigned packed = 0u;
        if (hi) {
            unsigned rel = __float_as_uint(best) - LOW;
            packed = ((rel + 1u) << 7) | (unsigned)bi;
            atomicAdd(&g_hist[bi], 1);
        }
        g_cp[i] = packed;               // generic path keeps direct scratch
        int cv = cur[i];
        out[i] = hi ? (cv != -1 ? (float)cv : (float)bi) : -1.0f;
        if (writeIdx) out[B + i] = (float)idx[i];
    }
}

__global__ void k2_init(int K, int PPC) { class_init_body(K, PPC); }

// ------------- selection kernel (rare path, software grid barriers) ---------
// needCP: K==128 path does not write g_cp in k1; recompute it here from c.
__global__ void kSel(const float* __restrict__ c,
                     const int*   __restrict__ cur,
                     float* __restrict__ out, int B, int K, int needCP) {
    __shared__ int s_na;
    if (threadIdx.x == 0) s_na = g_nactive;
    __syncthreads();
    if (s_na == 0) return;            // common case: early exit

    const unsigned LOW = __float_as_uint(ALPHA_F);
    const int stride = gridDim.x * blockDim.x;
    const int gtid = blockIdx.x * blockDim.x + threadIdx.x;
    const int lane = threadIdx.x & 31;

    // ---- pass 0 (K==128 only): recompute packed (rel+1)<<7|pred into g_cp ----
    if (needCP) {
        const int warpsTotal = stride >> 5;
        const int gwarp = gtid >> 5;
        for (int r = gwarp; r < B; r += warpsTotal) {
            const float4 v = reinterpret_cast<const float4*>(
                                 c + (size_t)r * 128)[lane];
            float cf; int pv;
            argmax_row(v, cf, pv);
            if (lane == 0) {
                unsigned packed = 0u;
                if (!(cf < ALPHA_F)) {
                    unsigned rel = __float_as_uint(cf) - LOW;
                    packed = ((rel + 1u) << 7) | (unsigned)pv;
                }
                g_cp[r] = packed;
            }
        }
        grid_barrier();
    }

    // ---- phase A: coarse 9-bit histogram ----
    for (int i = gtid; i < B; i += stride) {
        unsigned p = g_cp[i];
        if (!p) continue;
        int k = (int)(p & 127u);
        if (!g_active[k]) continue;
        atomicAdd(&g_h1[k * NBINS + ((p >> 7) >> 9)], 1);
    }
    grid_barrier();

    // ---- resolve A (block 0) ----
    if (blockIdx.x == 0) {
        int k = threadIdx.x;
        if (k < K && g_active[k]) {
            int rem = g_rem[k], cum = 0;
            for (int b = NBINS - 1; b >= 0; --b) {
                int cc = g_h1[k * NBINS + b];
                if (cum + cc >= rem) { g_sel1[k] = b; g_rem[k] = rem - cum; break; }
                cum += cc;
            }
        }
    }
    grid_barrier();

    // ---- phase B: fine 9-bit histogram ----
    for (int i = gtid; i < B; i += stride) {
        unsigned p = g_cp[i];
        if (!p) continue;
        int k = (int)(p & 127u);
        if (!g_active[k]) continue;
        unsigned relp = p >> 7;
        if ((int)(relp >> 9) != g_sel1[k]) continue;
        atomicAdd(&g_h2[k * NBINS + (relp & (NBINS - 1))], 1);
    }
    grid_barrier();

    // ---- resolve B (block 0): threshold + tie bookkeeping ----
    if (blockIdx.x == 0) {
        int k = threadIdx.x;
        int nt = 0;
        if (k < K && g_active[k]) {
            int rem = g_rem[k], cum = 0;
            for (int b = NBINS - 1; b >= 0; --b) {
                int cc = g_h2[k * NBINS + b];
                if (cum + cc >= rem) {
                    g_thrrel[k] = ((unsigned)g_sel1[k] << 9) | (unsigned)b;
                    int radmit = rem - cum;       // quota left inside tie group
                    g_radmit[k] = radmit;
                    if (cc > radmit) { g_needtie[k] = 1; nt = 1; }
                    break;
                }
                cum += cc;
            }
        }
        int total = __syncthreads_count(nt);
        if (threadIdx.x == 0) g_ntie = total;
    }
    grid_barrier();

    // ---- phase C: collect exact-threshold ties ----
    if (g_ntie) {
        for (int i = gtid; i < B; i += stride) {
            unsigned p = g_cp[i];
            if (!p) continue;
            int k = (int)(p & 127u);
            if (!g_needtie[k]) continue;
            if ((p >> 7) != g_thrrel[k]) continue;
            int pos = atomicAdd(&g_tiecnt[k], 1);
            if (pos < TIE_CAP) g_tied[k * TIE_CAP + pos] = i;
        }
        grid_barrier();
    }

    // ---- phase D: output fixup ----
    for (int i = gtid; i < B; i += stride) {
        unsigned p = g_cp[i];
        if (!p) continue;
        int k = (int)(p & 127u);
        if (!g_active[k]) continue;
        if (cur[i] != -1) continue;       // out already cur
        unsigned relp = p >> 7;
        unsigned thr  = g_thrrel[k];
        if (relp > thr) continue;         // admitted, out already pred
        if (relp < thr) { out[i] = -1.0f; continue; }
        if (!g_needtie[k]) continue;      // whole tie group admitted
        int cnt = g_tiecnt[k]; if (cnt > TIE_CAP) cnt = TIE_CAP;
        const int* lst = &g_tied[k * TIE_CAP];
        int t = 0;
        for (int j = 0; j < cnt; ++j) t += (lst[j] < i);
        out[i] = (t < g_radmit[k]) ? (float)k : -1.0f;
    }
    grid_barrier();

    // ---- cleanup: restore all-zero scratch invariant for next replay ----
    for (int j = gtid; j < KMAX * NBINS; j += stride) { g_h1[j] = 0; g_h2[j] = 0; }
    for (int j = gtid; j < KMAX; j += stride) { g_tiecnt[j] = 0; g_needtie[j] = 0; }
}

// -----------------------------------------------------------------------------
extern "C" void kernel_launch(void* const* d_in, const int* in_sizes, int n_in,
                              void* d_out, int out_size) {
    const float* c   = (const float*)d_in[0];
    const int*   cur = (const int*)d_in[1];
    const int*   idx = (const int*)d_in[2];
    float*       out = (float*)d_out;

    int B = in_sizes[1];
    int K = (B > 0) ? (int)((long long)in_sizes[0] / B) : 1;
    if (B <= 0 || B > BCAP || K <= 0 || K > KMAX) return;

    int PPC = (int)ceil((double)B / (double)K * 0.5);
    int writeIdx = (out_size >= 2 * B) ? 1 : 0;

    if (K == 128) {
        int nGroups = (B + 255) >> 8;
        int grid = nGroups < 1184 ? nGroups : 1184;
        k1_main<<<grid, 256>>>(c, cur, idx, out, B, writeIdx, K, PPC);
        kSel<<<NB_SEL, 256>>>(c, cur, out, B, K, /*needCP=*/1);
    } else {
        int grid = (B + 255) / 256;
        if (grid > 2048) grid = 2048;
        k1_generic<<<grid, 256>>>(c, cur, idx, out, B, K, writeIdx);
        k2_init<<<1, KMAX>>>(K, PPC);
        kSel<<<NB_SEL, 256>>>(c, cur, out, B, K, /*needCP=*/0);
    }
}

// round 11
// speedup vs baseline: 1.2130x; 1.2130x over previous
#include <cuda_runtime.h>
#include <stdint.h>
#include <math.h>

// ---------------------------------------------------------------------------
// InstanceLossBoost pseudo-label update.
//   inputs : c[B,K] f32, pseudo_label_cur[B] i32, index[B] i32   (K=128, B=2M)
//   output : float32 buffer = [ final[B] , index[B] ]  (values cast to float)
//
// Two launches (R9 structure, minus the scratch store):
//   k1_main : row argmax (warp/row, float4 streaming loads, REDUX, smem
//             staging), writes provisional output + per-class high-conf
//             histogram; last block performs class-init. NO scratch store.
//   kSel    : rare-path kernel (software grid barriers). If any class exceeds
//             the quota it RECOMPUTES packed (rel,pred) from c into g_cp, then
//             exact per-class top-PPC radix select (2 x 9-bit passes over
//             float bits in [bits(0.99), bits(1.0)]) + index tie-break +
//             output fixup. Early-exits otherwise; self-cleans all scratch.
// ---------------------------------------------------------------------------

#define ALPHA_F   0.99f
#define KMAX      256
#define NBINS     512
#define TIE_CAP   16384
#define BCAP      (1 << 22)
#define NB_SEL    32

// packed per-row scratch (rare path only): 0 if conf < alpha,
// else ((rel_bits + 1) << 7) | pred ; rel_bits = bits(conf) - bits(0.99f)
__device__ unsigned int  g_cp[BCAP];                 // 16 MB (rare path only)
__device__ int           g_hist[KMAX];               // zeroed by class-init
__device__ int           g_active[KMAX];
__device__ int           g_needtie[KMAX];            // zeroed by kSel cleanup
__device__ unsigned int  g_thrrel[KMAX];
__device__ int           g_radmit[KMAX];
__device__ int           g_sel1[KMAX];
__device__ int           g_rem[KMAX];
__device__ int           g_h1[KMAX * NBINS];         // zeroed by kSel cleanup
__device__ int           g_h2[KMAX * NBINS];         // zeroed by kSel cleanup
__device__ int           g_tiecnt[KMAX];             // zeroed by kSel cleanup
__device__ int           g_tied[KMAX * TIE_CAP];     // 16 MB
__device__ int           g_nactive;
__device__ int           g_ntie;
__device__ unsigned int  g_done1;                    // k1 completion counter
__device__ unsigned int  g_bar_cnt;
__device__ volatile unsigned int g_bar_gen;

// --------------------------- software grid barrier --------------------------
__device__ __forceinline__ void grid_barrier() {
    __syncthreads();
    if (threadIdx.x == 0) {
        __threadfence();
        unsigned gen = g_bar_gen;
        if (atomicAdd(&g_bar_cnt, 1) == gridDim.x - 1) {
            g_bar_cnt = 0;
            __threadfence();
            g_bar_gen = gen + 1;
        } else {
            while (g_bar_gen == gen) { }
            __threadfence();
        }
    }
    __syncthreads();
}

// ------------------ per-class init (fused into k1 tail) ---------------------
__device__ __forceinline__ void class_init_body(int K, int PPC) {
    int k = threadIdx.x;
    int act = 0;
    if (k < KMAX) {
        int h = (k < K) ? g_hist[k] : 0;
        g_hist[k]   = 0;                 // self-clean for next replay
        act = (h > PPC) ? 1 : 0;
        g_active[k] = act;
        g_thrrel[k] = 0u;
        g_rem[k]    = PPC;
        g_sel1[k]   = -1;
        g_radmit[k] = 0;
    }
    int na = __syncthreads_count(act);
    if (threadIdx.x == 0) g_nactive = na;
}

// ---------------------- warp argmax over one row (K=128) --------------------
// REDUX.max on float bits (softmax values non-negative) + ballot + 1 shuffle;
// tie rule = lowest column index (matches jnp.argmax).
__device__ __forceinline__ void argmax_row(const float4 v, float& conf, int& pred) {
    float m  = fmaxf(fmaxf(v.x, v.y), fmaxf(v.z, v.w));
    unsigned wb = __reduce_max_sync(0xffffffffu, __float_as_uint(m));
    float wm = __uint_as_float(wb);
    int local = 4;
    if (v.w == wm) local = 3;
    if (v.z == wm) local = 2;
    if (v.y == wm) local = 1;
    if (v.x == wm) local = 0;
    unsigned mask = __ballot_sync(0xffffffffu, local < 4);
    int src = __ffs(mask) - 1;
    int li  = __shfl_sync(0xffffffffu, local, src);
    conf = wm;
    pred = src * 4 + li;
}

__global__ void k1_main(const float* __restrict__ c,
                        const int*   __restrict__ cur,
                        const int*   __restrict__ idx,
                        float*       __restrict__ out,
                        int B, int writeIdx, int K, int PPC) {
    __shared__ float s_conf[256];
    __shared__ int   s_pred[256];
    __shared__ int   s_hist[128];
    __shared__ int   s_last;

    for (int t = threadIdx.x; t < 128; t += blockDim.x) s_hist[t] = 0;
    __syncthreads();

    const int warp = threadIdx.x >> 5;
    const int lane = threadIdx.x & 31;
    const int nChunks = (B + 255) >> 8;

    for (int chunk = blockIdx.x; chunk < nChunks; chunk += gridDim.x) {
        const int base  = chunk << 8;
        const int wbase = base + (warp << 5);
        const int i     = base + threadIdx.x;

        // prefetch staging operands under the row loads
        int cv = 0, iv = 0;
        if (i < B) {
            cv = __ldcs(cur + i);
            if (writeIdx) iv = __ldcs(idx + i);
        }

        if (base + 256 <= B) {
            // fast path: full chunk, 2 rows in flight, streaming loads
            #pragma unroll 2
            for (int t = 0; t < 32; t += 2) {
                const float4 a = __ldcs(reinterpret_cast<const float4*>(
                                     c + (size_t)(wbase + t) * 128) + lane);
                const float4 b = __ldcs(reinterpret_cast<const float4*>(
                                     c + (size_t)(wbase + t + 1) * 128) + lane);
                float c0, c1; int p0, p1;
                argmax_row(a, c0, p0);
                argmax_row(b, c1, p1);
                if (lane == 0) {
                    s_conf[(warp << 5) + t]     = c0;
                    s_pred[(warp << 5) + t]     = p0;
                    s_conf[(warp << 5) + t + 1] = c1;
                    s_pred[(warp << 5) + t + 1] = p1;
                }
            }
        } else {
            for (int t = 0; t < 32; ++t) {
                int r = wbase + t;
                if (r < B) {
                    const float4 v = __ldcs(reinterpret_cast<const float4*>(
                                         c + (size_t)r * 128) + lane);
                    float cf; int pv;
                    argmax_row(v, cf, pv);
                    if (lane == 0) {
                        s_conf[(warp << 5) + t] = cf;
                        s_pred[(warp << 5) + t] = pv;
                    }
                }
            }
        }
        __syncthreads();

        if (i < B) {
            float cf = s_conf[threadIdx.x];
            int   pv = s_pred[threadIdx.x];
            bool  hi = !(cf < ALPHA_F);
            if (hi) atomicAdd(&s_hist[pv], 1);
            __stcs(&out[i], hi ? (cv != -1 ? (float)cv : (float)pv) : -1.0f);
            if (writeIdx) __stcs(&out[B + i], (float)iv);
        }
        __syncthreads();
    }

    for (int t = threadIdx.x; t < 128; t += blockDim.x) {
        int v = s_hist[t];
        if (v) atomicAdd(&g_hist[t], v);
    }

    // ---- fused class init: last block to finish does it ----
    __threadfence();
    __syncthreads();
    if (threadIdx.x == 0) {
        unsigned t = atomicAdd(&g_done1, 1);
        s_last = (t == gridDim.x - 1) ? 1 : 0;
    }
    __syncthreads();
    if (s_last) {
        if (threadIdx.x == 0) g_done1 = 0;   // reset for next replay
        class_init_body(K, PPC);
    }
}

// --------------------- generic fallback (K != 128) --------------------------
__global__ void k1_generic(const float* __restrict__ c,
                           const int*   __restrict__ cur,
                           const int*   __restrict__ idx,
                           float*       __restrict__ out,
                           int B, int K, int writeIdx) {
    const unsigned LOW = __float_as_uint(ALPHA_F);
    int stride = gridDim.x * blockDim.x;
    for (int i = blockIdx.x * blockDim.x + threadIdx.x; i < B; i += stride) {
        const float* row = c + (size_t)i * K;
        float best = row[0]; int bi = 0;
        for (int j = 1; j < K; ++j) {
            float v = row[j];
            if (v > best) { best = v; bi = j; }
        }
        bool hi = !(best < ALPHA_F);
        unsigned packed = 0u;
        if (hi) {
            unsigned rel = __float_as_uint(best) - LOW;
            packed = ((rel + 1u) << 7) | (unsigned)bi;
            atomicAdd(&g_hist[bi], 1);
        }
        g_cp[i] = packed;               // generic path keeps direct scratch
        int cv = cur[i];
        out[i] = hi ? (cv != -1 ? (float)cv : (float)bi) : -1.0f;
        if (writeIdx) out[B + i] = (float)idx[i];
    }
}

__global__ void k2_init(int K, int PPC) { class_init_body(K, PPC); }

// ------------- selection kernel (rare path, software grid barriers) ---------
// needCP: K==128 path does not write g_cp in k1; recompute it here from c.
__global__ void kSel(const float* __restrict__ c,
                     const int*   __restrict__ cur,
                     float* __restrict__ out, int B, int K, int needCP) {
    __shared__ int s_na;
    if (threadIdx.x == 0) s_na = g_nactive;
    __syncthreads();
    if (s_na == 0) return;            // common case: early exit

    const unsigned LOW = __float_as_uint(ALPHA_F);
    const int stride = gridDim.x * blockDim.x;
    const int gtid = blockIdx.x * blockDim.x + threadIdx.x;
    const int lane = threadIdx.x & 31;

    // ---- pass 0 (K==128 only): recompute packed (rel+1)<<7|pred into g_cp ----
    if (needCP) {
        const int warpsTotal = stride >> 5;
        const int gwarp = gtid >> 5;
        for (int r = gwarp; r < B; r += warpsTotal) {
            const float4 v = reinterpret_cast<const float4*>(
                                 c + (size_t)r * 128)[lane];
            float cf; int pv;
            argmax_row(v, cf, pv);
            if (lane == 0) {
                unsigned packed = 0u;
                if (!(cf < ALPHA_F)) {
                    unsigned rel = __float_as_uint(cf) - LOW;
                    packed = ((rel + 1u) << 7) | (unsigned)pv;
                }
                g_cp[r] = packed;
            }
        }
        grid_barrier();
    }

    // ---- phase A: coarse 9-bit histogram ----
    for (int i = gtid; i < B; i += stride) {
        unsigned p = g_cp[i];
        if (!p) continue;
        int k = (int)(p & 127u);
        if (!g_active[k]) continue;
        atomicAdd(&g_h1[k * NBINS + ((p >> 7) >> 9)], 1);
    }
    grid_barrier();

    // ---- resolve A (block 0) ----
    if (blockIdx.x == 0) {
        int k = threadIdx.x;
        if (k < K && g_active[k]) {
            int rem = g_rem[k], cum = 0;
            for (int b = NBINS - 1; b >= 0; --b) {
                int cc = g_h1[k * NBINS + b];
                if (cum + cc >= rem) { g_sel1[k] = b; g_rem[k] = rem - cum; break; }
                cum += cc;
            }
        }
    }
    grid_barrier();

    // ---- phase B: fine 9-bit histogram ----
    for (int i = gtid; i < B; i += stride) {
        unsigned p = g_cp[i];
        if (!p) continue;
        int k = (int)(p & 127u);
        if (!g_active[k]) continue;
        unsigned relp = p >> 7;
        if ((int)(relp >> 9) != g_sel1[k]) continue;
        atomicAdd(&g_h2[k * NBINS + (relp & (NBINS - 1))], 1);
    }
    grid_barrier();

    // ---- resolve B (block 0): threshold + tie bookkeeping ----
    if (blockIdx.x == 0) {
        int k = threadIdx.x;
        int nt = 0;
        if (k < K && g_active[k]) {
            int rem = g_rem[k], cum = 0;
            for (int b = NBINS - 1; b >= 0; --b) {
                int cc = g_h2[k * NBINS + b];
                if (cum + cc >= rem) {
                    g_thrrel[k] = ((unsigned)g_sel1[k] << 9) | (unsigned)b;
                    int radmit = rem - cum;       // quota left inside tie group
                    g_radmit[k] = radmit;
                    if (cc > radmit) { g_needtie[k] = 1; nt = 1; }
                    break;
                }
                cum += cc;
            }
        }
        int total = __syncthreads_count(nt);
        if (threadIdx.x == 0) g_ntie = total;
    }
    grid_barrier();

    // ---- phase C: collect exact-threshold ties ----
    if (g_ntie) {
        for (int i = gtid; i < B; i += stride) {
            unsigned p = g_cp[i];
            if (!p) continue;
            int k = (int)(p & 127u);
            if (!g_needtie[k]) continue;
            if ((p >> 7) != g_thrrel[k]) continue;
            int pos = atomicAdd(&g_tiecnt[k], 1);
            if (pos < TIE_CAP) g_tied[k * TIE_CAP + pos] = i;
        }
        grid_barrier();
    }

    // ---- phase D: output fixup ----
    for (int i = gtid; i < B; i += stride) {
        unsigned p = g_cp[i];
        if (!p) continue;
        int k = (int)(p & 127u);
        if (!g_active[k]) continue;
        if (cur[i] != -1) continue;       // out already cur
        unsigned relp = p >> 7;
        unsigned thr  = g_thrrel[k];
        if (relp > thr) continue;         // admitted, out already pred
        if (relp < thr) { out[i] = -1.0f; continue; }
        if (!g_needtie[k]) continue;      // whole tie group admitted
        int cnt = g_tiecnt[k]; if (cnt > TIE_CAP) cnt = TIE_CAP;
        const int* lst = &g_tied[k * TIE_CAP];
        int t = 0;
        for (int j = 0; j < cnt; ++j) t += (lst[j] < i);
        out[i] = (t < g_radmit[k]) ? (float)k : -1.0f;
    }
    grid_barrier();

    // ---- cleanup: restore all-zero scratch invariant for next replay ----
    for (int j = gtid; j < KMAX * NBINS; j += stride) { g_h1[j] = 0; g_h2[j] = 0; }
    for (int j = gtid; j < KMAX; j += stride) { g_tiecnt[j] = 0; g_needtie[j] = 0; }
}

// -----------------------------------------------------------------------------
extern "C" void kernel_launch(void* const* d_in, const int* in_sizes, int n_in,
                              void* d_out, int out_size) {
    const float* c   = (const float*)d_in[0];
    const int*   cur = (const int*)d_in[1];
    const int*   idx = (const int*)d_in[2];
    float*       out = (float*)d_out;

    int B = in_sizes[1];
    int K = (B > 0) ? (int)((long long)in_sizes[0] / B) : 1;
    if (B <= 0 || B > BCAP || K <= 0 || K > KMAX) return;

    int PPC = (int)ceil((double)B / (double)K * 0.5);
    int writeIdx = (out_size >= 2 * B) ? 1 : 0;

    if (K == 128) {
        int nChunks = (B + 255) >> 8;
        int grid = nChunks < 1184 ? nChunks : 1184;
        k1_main<<<grid, 256>>>(c, cur, idx, out, B, writeIdx, K, PPC);
        kSel<<<NB_SEL, 256>>>(c, cur, out, B, K, /*needCP=*/1);
    } else {
        int grid = (B + 255) / 256;
        if (grid > 2048) grid = 2048;
        k1_generic<<<grid, 256>>>(c, cur, idx, out, B, K, writeIdx);
        k2_init<<<1, KMAX>>>(K, PPC);
        kSel<<<NB_SEL, 256>>>(c, cur, out, B, K, /*needCP=*/0);
    }
}